// round 2
// baseline (speedup 1.0000x reference)
#include <cuda_runtime.h>
#include <cuda_bf16.h>
#include <math.h>

#define N_NODES 50000
#define N_EDGES 600000
#define D 128
#define G 512
#define O 10

// Scratch (allocation-free rule: __device__ globals)
__device__ __align__(128) float g_A[N_NODES * D];   // hW buffer
__device__ __align__(128) float g_B[N_NODES * D];   // h / acc buffer (ping)
__device__ __align__(128) float g_dis[N_NODES];
__device__ __align__(128) int   g_cnt[N_NODES];
__device__ __align__(128) float g_pool[G * D];
__device__ __align__(128) float g_pcnt[G];

// ---------------------------------------------------------------------------
// init: zero cnt / pool / pcnt
// ---------------------------------------------------------------------------
__global__ void k_init_zero() {
    int i = blockIdx.x * blockDim.x + threadIdx.x;
    if (i < N_NODES) g_cnt[i] = 0;
    if (i < G * D)   g_pool[i] = 0.0f;
    if (i < G)       g_pcnt[i] = 0.0f;
}

// count in-degree over dst (col); self-loop handled as +1 later
__global__ void k_count(const int* __restrict__ ei) {
    int e = blockIdx.x * blockDim.x + threadIdx.x;
    if (e < N_EDGES) {
        int d = ei[N_EDGES + e];  // dst row of edge_index
        atomicAdd(&g_cnt[d], 1);
    }
}

__global__ void k_dis() {
    int i = blockIdx.x * blockDim.x + threadIdx.x;
    if (i < N_NODES) g_dis[i] = rsqrtf((float)g_cnt[i] + 1.0f);
}

__global__ void k_pcount(const int* __restrict__ batch) {
    int i = blockIdx.x * blockDim.x + threadIdx.x;
    if (i < N_NODES) atomicAdd(&g_pcnt[batch[i]], 1.0f);
}

// ---------------------------------------------------------------------------
// GEMM: g_A = in @ W   (in = x if use_x else g_B), [n x 128] @ [128 x 128]
// BM=64, BK=32, BN=128, 256 threads, 8x4 per-thread tile
// ---------------------------------------------------------------------------
__global__ void k_gemm128(const float* __restrict__ Xin, const float* __restrict__ W,
                          int use_x, int n) {
    __shared__ float As[64][33];
    __shared__ float Ws[32][128];
    const float* A = use_x ? Xin : (const float*)g_B;

    int tid  = threadIdx.x;
    int row0 = blockIdx.x * 64;
    int cx   = tid & 31;   // column group (4 cols)
    int ry   = tid >> 5;   // row group (8 rows)

    float acc[8][4];
#pragma unroll
    for (int r = 0; r < 8; r++)
#pragma unroll
        for (int c = 0; c < 4; c++) acc[r][c] = 0.0f;

    for (int k0 = 0; k0 < D; k0 += 32) {
        // load A tile 64x32 (512 float4, 2 per thread)
#pragma unroll
        for (int i = 0; i < 2; i++) {
            int f = tid + i * 256;
            int r = f >> 3, k4 = f & 7;
            int row = row0 + r;
            float4 v = make_float4(0.f, 0.f, 0.f, 0.f);
            if (row < n) v = *(const float4*)(A + (size_t)row * D + k0 + k4 * 4);
            As[r][k4 * 4 + 0] = v.x; As[r][k4 * 4 + 1] = v.y;
            As[r][k4 * 4 + 2] = v.z; As[r][k4 * 4 + 3] = v.w;
        }
        // load W tile 32x128 (1024 float4, 4 per thread)
#pragma unroll
        for (int i = 0; i < 4; i++) {
            int f = tid + i * 256;
            int kk = f >> 5, c4 = f & 31;
            float4 v = *(const float4*)(W + (size_t)(k0 + kk) * D + c4 * 4);
            *(float4*)&Ws[kk][c4 * 4] = v;
        }
        __syncthreads();
#pragma unroll
        for (int kk = 0; kk < 32; kk++) {
            float4 b = *(const float4*)&Ws[kk][cx * 4];
#pragma unroll
            for (int r = 0; r < 8; r++) {
                float a = As[ry * 8 + r][kk];
                acc[r][0] += a * b.x; acc[r][1] += a * b.y;
                acc[r][2] += a * b.z; acc[r][3] += a * b.w;
            }
        }
        __syncthreads();
    }
#pragma unroll
    for (int r = 0; r < 8; r++) {
        int row = row0 + ry * 8 + r;
        if (row < n)
            *(float4*)(g_A + (size_t)row * D + cx * 4) =
                make_float4(acc[r][0], acc[r][1], acc[r][2], acc[r][3]);
    }
}

// ---------------------------------------------------------------------------
// zero acc buffer (g_B)
// ---------------------------------------------------------------------------
__global__ void k_zeroB() {
    int i = blockIdx.x * blockDim.x + threadIdx.x;
    if (i < N_NODES * (D / 4))
        ((float4*)g_B)[i] = make_float4(0.f, 0.f, 0.f, 0.f);
}

// ---------------------------------------------------------------------------
// edge scatter: one warp per edge; lane handles one float4 of the 128-d row
// g_B[dst] += norm * g_A[src]
// ---------------------------------------------------------------------------
__global__ void k_scatter(const int* __restrict__ ei) {
    int gtid = blockIdx.x * blockDim.x + threadIdx.x;
    int e = gtid >> 5;
    if (e >= N_EDGES) return;
    int lane = gtid & 31;
    int s = ei[e];
    int d = ei[N_EDGES + e];
    float nrm = g_dis[s] * g_dis[d];
    float4 v = ((const float4*)(g_A + (size_t)s * D))[lane];
    v.x *= nrm; v.y *= nrm; v.z *= nrm; v.w *= nrm;
    float* out = g_B + (size_t)d * D + lane * 4;
    asm volatile("red.global.add.v4.f32 [%0], {%1,%2,%3,%4};"
                 :: "l"(out), "f"(v.x), "f"(v.y), "f"(v.z), "f"(v.w)
                 : "memory");
}

// ---------------------------------------------------------------------------
// finalize: g_B = relu(g_B + dis^2 * g_A + bias); optionally pool-accumulate
// ---------------------------------------------------------------------------
__global__ void k_finalize(const float* __restrict__ bias,
                           const int* __restrict__ batch, int doPool) {
    int t = blockIdx.x * blockDim.x + threadIdx.x;
    if (t >= N_NODES * (D / 4)) return;
    int i = t >> 5, j = t & 31;
    float dv = g_dis[i];
    float d2 = dv * dv;
    float4 a = ((float4*)g_B)[t];
    float4 h = ((const float4*)g_A)[t];
    float4 bb = ((const float4*)bias)[j];
    float4 v;
    v.x = fmaxf(a.x + d2 * h.x + bb.x, 0.f);
    v.y = fmaxf(a.y + d2 * h.y + bb.y, 0.f);
    v.z = fmaxf(a.z + d2 * h.z + bb.z, 0.f);
    v.w = fmaxf(a.w + d2 * h.w + bb.w, 0.f);
    ((float4*)g_B)[t] = v;
    if (doPool) {
        int gidx = batch[i];
        float* pp = g_pool + (size_t)gidx * D + j * 4;
        asm volatile("red.global.add.v4.f32 [%0], {%1,%2,%3,%4};"
                     :: "l"(pp), "f"(v.x), "f"(v.y), "f"(v.z), "f"(v.w)
                     : "memory");
    }
}

// ---------------------------------------------------------------------------
// head: pooled mean -> linear(128->10) -> log_softmax. One warp per graph.
// ---------------------------------------------------------------------------
__global__ void k_head(const float* __restrict__ Wf, const float* __restrict__ bf,
                       float* __restrict__ out) {
    int g = blockIdx.x;
    int lane = threadIdx.x;
    float inv = 1.0f / fmaxf(g_pcnt[g], 1.0f);
    float logit = -INFINITY;
    if (lane < O) {
        float s = bf[lane];
        const float* pr = g_pool + (size_t)g * D;
#pragma unroll 8
        for (int k = 0; k < D; k++)
            s += pr[k] * inv * Wf[k * O + lane];
        logit = s;
    }
    float m = logit;
#pragma unroll
    for (int o = 16; o; o >>= 1) m = fmaxf(m, __shfl_xor_sync(0xffffffffu, m, o));
    float e = (lane < O) ? expf(logit - m) : 0.0f;
    float se = e;
#pragma unroll
    for (int o = 16; o; o >>= 1) se += __shfl_xor_sync(0xffffffffu, se, o);
    if (lane < O) out[g * O + lane] = logit - m - logf(se);
}

// ---------------------------------------------------------------------------
extern "C" void kernel_launch(void* const* d_in, const int* in_sizes, int n_in,
                              void* d_out, int out_size) {
    const float* x     = (const float*)d_in[0];
    const int*   ei    = (const int*)d_in[1];
    const int*   batch = (const int*)d_in[2];
    const float* W0 = (const float*)d_in[3];
    const float* b0 = (const float*)d_in[4];
    const float* W1 = (const float*)d_in[5];
    const float* b1 = (const float*)d_in[6];
    const float* W2 = (const float*)d_in[7];
    const float* b2 = (const float*)d_in[8];
    const float* Wf = (const float*)d_in[9];
    const float* bf = (const float*)d_in[10];
    float* out = (float*)d_out;

    const int n = N_NODES;

    // degree / norm / pool counts
    k_init_zero<<<(G * D + 255) / 256, 256>>>();
    k_count<<<(N_EDGES + 255) / 256, 256>>>(ei);
    k_dis<<<(n + 255) / 256, 256>>>();
    k_pcount<<<(n + 255) / 256, 256>>>(batch);

    const float* Ws[3] = {W0, W1, W2};
    const float* bs[3] = {b0, b1, b2};

    int gemm_blocks  = (n + 63) / 64;
    int vec_blocks   = (n * (D / 4) + 255) / 256;
    int scat_blocks  = (N_EDGES * 32 + 255) / 256;

    for (int l = 0; l < 3; l++) {
        k_gemm128<<<gemm_blocks, 256>>>(x, Ws[l], l == 0 ? 1 : 0, n);
        k_zeroB<<<vec_blocks, 256>>>();
        k_scatter<<<scat_blocks, 256>>>(ei);
        k_finalize<<<vec_blocks, 256>>>(bs[l], batch, l == 2 ? 1 : 0);
    }

    k_head<<<G, 32>>>(Wf, bf, out);
}

// round 3
// speedup vs baseline: 1.4582x; 1.4582x over previous
#include <cuda_runtime.h>
#include <cuda_bf16.h>
#include <math.h>

#define N_NODES 50000
#define N_EDGES 600000
#define D 128
#define G 512
#define O 10
#define NBLK 196   // ceil(50000/256)

// Scratch (allocation-free rule: __device__ globals)
__device__ __align__(128) float g_A[N_NODES * D];   // hW buffer
__device__ __align__(128) float g_B[N_NODES * D];   // h buffer
__device__ __align__(128) float g_dis[N_NODES];
__device__ __align__(128) int   g_cnt[N_NODES];
__device__ __align__(128) int   g_rowptr[N_NODES];
__device__ __align__(128) int   g_cursor[N_NODES];
__device__ __align__(128) int   g_csrc[N_EDGES];
__device__ __align__(128) float g_cnrm[N_EDGES];
__device__ __align__(128) int   g_bsum[NBLK];
__device__ __align__(128) int   g_boff[NBLK];
__device__ __align__(128) float g_pool[G * D];
__device__ __align__(128) float g_pcnt[G];

// ---------------------------------------------------------------------------
// prep: zero cnt + pool
// ---------------------------------------------------------------------------
__global__ void k_prep() {
    int i = blockIdx.x * blockDim.x + threadIdx.x;
    if (i < N_NODES) g_cnt[i] = 0;
    if (i < G * D)   g_pool[i] = 0.0f;
}

// count in-degree over dst
__global__ void k_count(const int* __restrict__ ei) {
    int e = blockIdx.x * blockDim.x + threadIdx.x;
    if (e < N_EDGES) atomicAdd(&g_cnt[ei[N_EDGES + e]], 1);
}

// ---------------------------------------------------------------------------
// 3-phase exclusive scan of g_cnt -> g_rowptr ; also compute dis
// ---------------------------------------------------------------------------
__global__ void k_scan1() {
    __shared__ int s[256];
    int t = threadIdx.x;
    int i = blockIdx.x * 256 + t;
    int v = (i < N_NODES) ? g_cnt[i] : 0;
    if (i < N_NODES) g_dis[i] = rsqrtf((float)v + 1.0f);
    s[t] = v;
#pragma unroll
    for (int off = 1; off < 256; off <<= 1) {
        __syncthreads();
        int tmp = (t >= off) ? s[t - off] : 0;
        __syncthreads();
        s[t] += tmp;
    }
    if (i < N_NODES) g_rowptr[i] = s[t] - v;        // local exclusive
    if (t == 255) g_bsum[blockIdx.x] = s[255];
}

__global__ void k_scan2() {
    __shared__ int s[256];
    int t = threadIdx.x;
    int v = (t < NBLK) ? g_bsum[t] : 0;
    s[t] = v;
#pragma unroll
    for (int off = 1; off < 256; off <<= 1) {
        __syncthreads();
        int tmp = (t >= off) ? s[t - off] : 0;
        __syncthreads();
        s[t] += tmp;
    }
    if (t < NBLK) g_boff[t] = s[t] - v;             // exclusive
}

__global__ void k_scan3() {
    int i = blockIdx.x * 256 + threadIdx.x;
    if (i < N_NODES) {
        int r = g_rowptr[i] + g_boff[blockIdx.x];
        g_rowptr[i] = r;
        g_cursor[i] = r;
    }
}

// fill CSR: src index + precomputed norm per edge
__global__ void k_fill(const int* __restrict__ ei) {
    int e = blockIdx.x * blockDim.x + threadIdx.x;
    if (e >= N_EDGES) return;
    int s = ei[e];
    int d = ei[N_EDGES + e];
    int pos = atomicAdd(&g_cursor[d], 1);
    g_csrc[pos] = s;
    g_cnrm[pos] = g_dis[s] * g_dis[d];
}

// per-graph node counts via binary search (batch is sorted)
__global__ void k_pcnt(const int* __restrict__ batch) {
    int g = blockIdx.x * blockDim.x + threadIdx.x;
    if (g >= G) return;
    int lo = 0, hi = N_NODES;
    while (lo < hi) { int m = (lo + hi) >> 1; if (batch[m] < g) lo = m + 1; else hi = m; }
    int lb = lo;
    lo = 0; hi = N_NODES;
    while (lo < hi) { int m = (lo + hi) >> 1; if (batch[m] <= g) lo = m + 1; else hi = m; }
    g_pcnt[g] = (float)(lo - lb);
}

// ---------------------------------------------------------------------------
// GEMM: g_A = in @ W   (in = x if use_x else g_B)
// BM=128, BN=128, BK=16, 256 threads, 8x8 per-thread tile
// ---------------------------------------------------------------------------
__global__ void __launch_bounds__(256, 2) k_gemm128(const float* __restrict__ Xin,
                                                    const float* __restrict__ W,
                                                    int use_x, int n) {
    __shared__ float As[16][136];  // [k][row]
    __shared__ float Ws[16][136];  // [k][col]
    const float* A = use_x ? Xin : (const float*)g_B;

    int tid  = threadIdx.x;
    int row0 = blockIdx.x * 128;
    int tx = tid & 15, ty = tid >> 4;

    float acc[8][8];
#pragma unroll
    for (int r = 0; r < 8; r++)
#pragma unroll
        for (int c = 0; c < 8; c++) acc[r][c] = 0.0f;

    for (int k0 = 0; k0 < D; k0 += 16) {
        // A tile: 128 rows x 16 k (512 float4, 2/thread), stored transposed
#pragma unroll
        for (int i = 0; i < 2; i++) {
            int f = tid + i * 256;
            int r = f >> 2, kq = f & 3;
            int row = row0 + r;
            float4 v = make_float4(0.f, 0.f, 0.f, 0.f);
            if (row < n) v = *(const float4*)(A + (size_t)row * D + k0 + kq * 4);
            As[kq * 4 + 0][r] = v.x; As[kq * 4 + 1][r] = v.y;
            As[kq * 4 + 2][r] = v.z; As[kq * 4 + 3][r] = v.w;
        }
        // W tile: 16 k x 128 cols (512 float4, 2/thread)
#pragma unroll
        for (int i = 0; i < 2; i++) {
            int f = tid + i * 256;
            int kk = f >> 5, c4 = f & 31;
            float4 v = *(const float4*)(W + (size_t)(k0 + kk) * D + c4 * 4);
            *(float4*)&Ws[kk][c4 * 4] = v;
        }
        __syncthreads();
#pragma unroll
        for (int kk = 0; kk < 16; kk++) {
            float a[8], b[8];
            *(float4*)&a[0] = *(const float4*)&As[kk][ty * 8];
            *(float4*)&a[4] = *(const float4*)&As[kk][ty * 8 + 4];
            *(float4*)&b[0] = *(const float4*)&Ws[kk][tx * 8];
            *(float4*)&b[4] = *(const float4*)&Ws[kk][tx * 8 + 4];
#pragma unroll
            for (int r = 0; r < 8; r++)
#pragma unroll
                for (int c = 0; c < 8; c++)
                    acc[r][c] += a[r] * b[c];
        }
        __syncthreads();
    }
#pragma unroll
    for (int r = 0; r < 8; r++) {
        int row = row0 + ty * 8 + r;
        if (row < n) {
            *(float4*)(g_A + (size_t)row * D + tx * 8) =
                make_float4(acc[r][0], acc[r][1], acc[r][2], acc[r][3]);
            *(float4*)(g_A + (size_t)row * D + tx * 8 + 4) =
                make_float4(acc[r][4], acc[r][5], acc[r][6], acc[r][7]);
        }
    }
}

// ---------------------------------------------------------------------------
// fused aggregate: warp per node.
// g_B[i] = relu( dis_i^2 * g_A[i] + sum_{e: dst=i} nrm_e * g_A[src_e] + bias )
// optionally RED into pool.
// ---------------------------------------------------------------------------
__global__ void k_agg(const float* __restrict__ bias,
                      const int* __restrict__ batch, int doPool) {
    int gt = blockIdx.x * blockDim.x + threadIdx.x;
    int w = gt >> 5;
    if (w >= N_NODES) return;
    int lane = gt & 31;

    float dv = g_dis[w];
    float sn = dv * dv;
    float4 h = ((const float4*)(g_A + (size_t)w * D))[lane];
    float4 acc = make_float4(sn * h.x, sn * h.y, sn * h.z, sn * h.w);

    int beg = g_rowptr[w];
    int end = beg + g_cnt[w];
    for (int k = beg; k < end; k++) {
        int s = g_csrc[k];
        float nr = g_cnrm[k];
        float4 v = ((const float4*)(g_A + (size_t)s * D))[lane];
        acc.x += nr * v.x; acc.y += nr * v.y;
        acc.z += nr * v.z; acc.w += nr * v.w;
    }

    float4 bb = ((const float4*)bias)[lane];
    acc.x = fmaxf(acc.x + bb.x, 0.f);
    acc.y = fmaxf(acc.y + bb.y, 0.f);
    acc.z = fmaxf(acc.z + bb.z, 0.f);
    acc.w = fmaxf(acc.w + bb.w, 0.f);
    ((float4*)(g_B + (size_t)w * D))[lane] = acc;

    if (doPool) {
        float* pp = g_pool + (size_t)batch[w] * D + lane * 4;
        asm volatile("red.global.add.v4.f32 [%0], {%1,%2,%3,%4};"
                     :: "l"(pp), "f"(acc.x), "f"(acc.y), "f"(acc.z), "f"(acc.w)
                     : "memory");
    }
}

// ---------------------------------------------------------------------------
// head: pooled mean -> linear(128->10) -> log_softmax. One warp per graph.
// ---------------------------------------------------------------------------
__global__ void k_head(const float* __restrict__ Wf, const float* __restrict__ bf,
                       float* __restrict__ out) {
    int g = blockIdx.x;
    int lane = threadIdx.x;
    float inv = 1.0f / fmaxf(g_pcnt[g], 1.0f);
    float logit = -INFINITY;
    if (lane < O) {
        float s = bf[lane];
        const float* pr = g_pool + (size_t)g * D;
#pragma unroll 8
        for (int k = 0; k < D; k++)
            s += pr[k] * inv * Wf[k * O + lane];
        logit = s;
    }
    float m = logit;
#pragma unroll
    for (int o = 16; o; o >>= 1) m = fmaxf(m, __shfl_xor_sync(0xffffffffu, m, o));
    float e = (lane < O) ? expf(logit - m) : 0.0f;
    float se = e;
#pragma unroll
    for (int o = 16; o; o >>= 1) se += __shfl_xor_sync(0xffffffffu, se, o);
    if (lane < O) out[g * O + lane] = logit - m - logf(se);
}

// ---------------------------------------------------------------------------
extern "C" void kernel_launch(void* const* d_in, const int* in_sizes, int n_in,
                              void* d_out, int out_size) {
    const float* x     = (const float*)d_in[0];
    const int*   ei    = (const int*)d_in[1];
    const int*   batch = (const int*)d_in[2];
    const float* W0 = (const float*)d_in[3];
    const float* b0 = (const float*)d_in[4];
    const float* W1 = (const float*)d_in[5];
    const float* b1 = (const float*)d_in[6];
    const float* W2 = (const float*)d_in[7];
    const float* b2 = (const float*)d_in[8];
    const float* Wf = (const float*)d_in[9];
    const float* bf = (const float*)d_in[10];
    float* out = (float*)d_out;

    // build degree / dis / CSR / pool counts
    k_prep<<<(G * D + 255) / 256, 256>>>();
    k_count<<<(N_EDGES + 255) / 256, 256>>>(ei);
    k_scan1<<<NBLK, 256>>>();
    k_scan2<<<1, 256>>>();
    k_scan3<<<NBLK, 256>>>();
    k_fill<<<(N_EDGES + 255) / 256, 256>>>(ei);
    k_pcnt<<<(G + 255) / 256, 256>>>(batch);

    const float* Ws[3] = {W0, W1, W2};
    const float* bs[3] = {b0, b1, b2};

    int gemm_blocks = (N_NODES + 127) / 128;
    int agg_blocks  = (N_NODES * 32 + 255) / 256;

    for (int l = 0; l < 3; l++) {
        k_gemm128<<<gemm_blocks, 256>>>(x, Ws[l], l == 0 ? 1 : 0, N_NODES);
        k_agg<<<agg_blocks, 256>>>(bs[l], batch, l == 2 ? 1 : 0);
    }

    k_head<<<G, 32>>>(Wf, bf, out);
}

// round 5
// speedup vs baseline: 1.7770x; 1.2187x over previous
#include <cuda_runtime.h>
#include <cuda_bf16.h>
#include <math.h>
#include <stdint.h>

#define N_NODES 50000
#define N_EDGES 600000
#define D 128
#define G 512
#define O 10
#define NBLK 196               // ceil(50000/256)
#define GEMM_TILES 391         // ceil(50000/128)

// Scratch (allocation-free rule: __device__ globals)
__device__ __align__(128) float g_A[N_NODES * D];   // hW buffer
__device__ __align__(128) float g_B[N_NODES * D];   // h buffer
__device__ __align__(128) float g_dis[N_NODES];
__device__ __align__(128) int   g_cnt[N_NODES];
__device__ __align__(128) int   g_rowptr[N_NODES];
__device__ __align__(128) int   g_cursor[N_NODES];
__device__ __align__(128) int   g_csrc[N_EDGES];
__device__ __align__(128) float g_cnrm[N_EDGES];
__device__ __align__(128) int   g_bsum[NBLK];
__device__ __align__(128) int   g_boff[NBLK];
__device__ __align__(128) float g_pool[G * D];
__device__ __align__(128) float g_pcnt[G];

// ---------------------------------------------------------------------------
// prep: zero cnt + pool
// ---------------------------------------------------------------------------
__global__ void k_prep() {
    int i = blockIdx.x * blockDim.x + threadIdx.x;
    if (i < N_NODES) g_cnt[i] = 0;
    if (i < G * D)   g_pool[i] = 0.0f;
}

__global__ void k_count(const int* __restrict__ ei) {
    int e = blockIdx.x * blockDim.x + threadIdx.x;
    if (e < N_EDGES) atomicAdd(&g_cnt[ei[N_EDGES + e]], 1);
}

// 3-phase exclusive scan of g_cnt -> g_rowptr ; also compute dis
__global__ void k_scan1() {
    __shared__ int s[256];
    int t = threadIdx.x;
    int i = blockIdx.x * 256 + t;
    int v = (i < N_NODES) ? g_cnt[i] : 0;
    if (i < N_NODES) g_dis[i] = rsqrtf((float)v + 1.0f);
    s[t] = v;
#pragma unroll
    for (int off = 1; off < 256; off <<= 1) {
        __syncthreads();
        int tmp = (t >= off) ? s[t - off] : 0;
        __syncthreads();
        s[t] += tmp;
    }
    if (i < N_NODES) g_rowptr[i] = s[t] - v;
    if (t == 255) g_bsum[blockIdx.x] = s[255];
}

__global__ void k_scan2() {
    __shared__ int s[256];
    int t = threadIdx.x;
    int v = (t < NBLK) ? g_bsum[t] : 0;
    s[t] = v;
#pragma unroll
    for (int off = 1; off < 256; off <<= 1) {
        __syncthreads();
        int tmp = (t >= off) ? s[t - off] : 0;
        __syncthreads();
        s[t] += tmp;
    }
    if (t < NBLK) g_boff[t] = s[t] - v;
}

__global__ void k_scan3() {
    int i = blockIdx.x * 256 + threadIdx.x;
    if (i < N_NODES) {
        int r = g_rowptr[i] + g_boff[blockIdx.x];
        g_rowptr[i] = r;
        g_cursor[i] = r;
    }
}

__global__ void k_fill(const int* __restrict__ ei) {
    int e = blockIdx.x * blockDim.x + threadIdx.x;
    if (e >= N_EDGES) return;
    int s = ei[e];
    int d = ei[N_EDGES + e];
    int pos = atomicAdd(&g_cursor[d], 1);
    g_csrc[pos] = s;
    g_cnrm[pos] = g_dis[s] * g_dis[d];
}

__global__ void k_pcnt(const int* __restrict__ batch) {
    int g = blockIdx.x * blockDim.x + threadIdx.x;
    if (g >= G) return;
    int lo = 0, hi = N_NODES;
    while (lo < hi) { int m = (lo + hi) >> 1; if (batch[m] < g) lo = m + 1; else hi = m; }
    int lb = lo;
    lo = 0; hi = N_NODES;
    while (lo < hi) { int m = (lo + hi) >> 1; if (batch[m] <= g) lo = m + 1; else hi = m; }
    g_pcnt[g] = (float)(lo - lb);
}

// ---------------------------------------------------------------------------
// tf32 split helpers (3xTF32 scheme: ~2^-21 effective precision)
// ---------------------------------------------------------------------------
__device__ __forceinline__ void split_tf32(float v, uint32_t& hi, uint32_t& lo) {
    uint32_t h;
    asm("cvt.rna.tf32.f32 %0, %1;" : "=r"(h) : "f"(v));
    float l = v - __uint_as_float(h);
    uint32_t l32;
    asm("cvt.rna.tf32.f32 %0, %1;" : "=r"(l32) : "f"(l));
    hi = h; lo = l32;
}

__device__ __forceinline__ void mma_tf32(float* c, const uint32_t* a, const uint32_t* b) {
    asm volatile(
        "mma.sync.aligned.m16n8k8.row.col.f32.tf32.tf32.f32 "
        "{%0,%1,%2,%3}, {%4,%5,%6,%7}, {%8,%9}, {%0,%1,%2,%3};"
        : "+f"(c[0]), "+f"(c[1]), "+f"(c[2]), "+f"(c[3])
        : "r"(a[0]), "r"(a[1]), "r"(a[2]), "r"(a[3]), "r"(b[0]), "r"(b[1]));
}

// ---------------------------------------------------------------------------
// GEMM via mma.sync tf32 (3xTF32): g_A = in @ W  (in = x if use_x else g_B)
// BM=128, BN=128, BK=32 x 4 phases. 256 threads = 8 warps (2m x 4n),
// warp tile 64x32 (4 m16-tiles x 4 n8-tiles). Smem: Ahi/Alo stride 36,
// Bhi/Blo stride 136 (both bank-conflict-free for the fragment patterns).
// ---------------------------------------------------------------------------
#define A_STRIDE 36
#define B_STRIDE 136
#define SM_AHI 0
#define SM_ALO (128 * A_STRIDE)            // floats
#define SM_BHI (2 * 128 * A_STRIDE)
#define SM_BLO (2 * 128 * A_STRIDE + 32 * B_STRIDE)
#define SMEM_GEMM_FLOATS (2 * 128 * A_STRIDE + 2 * 32 * B_STRIDE)
#define SMEM_GEMM_BYTES (SMEM_GEMM_FLOATS * 4)

__global__ void __launch_bounds__(256, 2) k_gemm_tc(const float* __restrict__ Xin,
                                                    const float* __restrict__ W,
                                                    int use_x, int n) {
    extern __shared__ float sm[];
    const float* A = use_x ? Xin : (const float*)g_B;

    int tid = threadIdx.x;
    int wid = tid >> 5, lane = tid & 31;
    int warp_m = wid >> 2, warp_n = wid & 3;
    int lg = lane >> 2, lt = lane & 3;     // groupID, threadID_in_group
    int row0 = blockIdx.x * 128;

    float acc[4][4][4];
#pragma unroll
    for (int mt = 0; mt < 4; mt++)
#pragma unroll
        for (int nt = 0; nt < 4; nt++)
#pragma unroll
            for (int q = 0; q < 4; q++) acc[mt][nt][q] = 0.0f;

    for (int p = 0; p < 4; p++) {
        int k0 = p * 32;
        // stage A chunk: 128 rows x 32 cols = 1024 float4s, 4 per thread
#pragma unroll
        for (int i = 0; i < 4; i++) {
            int idx = tid + i * 256;
            int row = idx >> 3, cq = idx & 7;
            int gr = row0 + row;
            float4 v = make_float4(0.f, 0.f, 0.f, 0.f);
            if (gr < n) v = *(const float4*)(A + (size_t)gr * D + k0 + cq * 4);
            uint4 hi, lo;
            split_tf32(v.x, hi.x, lo.x); split_tf32(v.y, hi.y, lo.y);
            split_tf32(v.z, hi.z, lo.z); split_tf32(v.w, hi.w, lo.w);
            *(uint4*)&sm[SM_AHI + row * A_STRIDE + cq * 4] = hi;
            *(uint4*)&sm[SM_ALO + row * A_STRIDE + cq * 4] = lo;
        }
        // stage B chunk: 32 k-rows x 128 cols = 1024 float4s, 4 per thread
#pragma unroll
        for (int i = 0; i < 4; i++) {
            int idx = tid + i * 256;
            int kk = idx >> 5, nq = idx & 31;
            float4 v = *(const float4*)(W + (size_t)(k0 + kk) * D + nq * 4);
            uint4 hi, lo;
            split_tf32(v.x, hi.x, lo.x); split_tf32(v.y, hi.y, lo.y);
            split_tf32(v.z, hi.z, lo.z); split_tf32(v.w, hi.w, lo.w);
            *(uint4*)&sm[SM_BHI + kk * B_STRIDE + nq * 4] = hi;
            *(uint4*)&sm[SM_BLO + kk * B_STRIDE + nq * 4] = lo;
        }
        __syncthreads();

#pragma unroll
        for (int kk = 0; kk < 4; kk++) {
            int kb = kk * 8;
            // B fragments for 4 n-tiles (hi + lo)
            uint32_t bhi[4][2], blo[4][2];
#pragma unroll
            for (int nt = 0; nt < 4; nt++) {
                int col = warp_n * 32 + nt * 8 + lg;
                bhi[nt][0] = __float_as_uint(sm[SM_BHI + (kb + lt) * B_STRIDE + col]);
                bhi[nt][1] = __float_as_uint(sm[SM_BHI + (kb + lt + 4) * B_STRIDE + col]);
                blo[nt][0] = __float_as_uint(sm[SM_BLO + (kb + lt) * B_STRIDE + col]);
                blo[nt][1] = __float_as_uint(sm[SM_BLO + (kb + lt + 4) * B_STRIDE + col]);
            }
#pragma unroll
            for (int mt = 0; mt < 4; mt++) {
                int rbase = warp_m * 64 + mt * 16;
                uint32_t ahi[4], alo[4];
                ahi[0] = __float_as_uint(sm[SM_AHI + (rbase + lg) * A_STRIDE + kb + lt]);
                ahi[1] = __float_as_uint(sm[SM_AHI + (rbase + lg + 8) * A_STRIDE + kb + lt]);
                ahi[2] = __float_as_uint(sm[SM_AHI + (rbase + lg) * A_STRIDE + kb + lt + 4]);
                ahi[3] = __float_as_uint(sm[SM_AHI + (rbase + lg + 8) * A_STRIDE + kb + lt + 4]);
                alo[0] = __float_as_uint(sm[SM_ALO + (rbase + lg) * A_STRIDE + kb + lt]);
                alo[1] = __float_as_uint(sm[SM_ALO + (rbase + lg + 8) * A_STRIDE + kb + lt]);
                alo[2] = __float_as_uint(sm[SM_ALO + (rbase + lg) * A_STRIDE + kb + lt + 4]);
                alo[3] = __float_as_uint(sm[SM_ALO + (rbase + lg + 8) * A_STRIDE + kb + lt + 4]);
#pragma unroll
                for (int nt = 0; nt < 4; nt++) {
                    mma_tf32(acc[mt][nt], ahi, bhi[nt]);   // hi*hi
                    mma_tf32(acc[mt][nt], alo, bhi[nt]);   // lo*hi
                    mma_tf32(acc[mt][nt], ahi, blo[nt]);   // hi*lo
                }
            }
        }
        __syncthreads();
    }

    // epilogue: write to g_A
#pragma unroll
    for (int mt = 0; mt < 4; mt++) {
        int r0 = row0 + warp_m * 64 + mt * 16 + lg;
#pragma unroll
        for (int nt = 0; nt < 4; nt++) {
            int col = warp_n * 32 + nt * 8 + 2 * lt;
            if (r0 < n)
                *(float2*)(g_A + (size_t)r0 * D + col) =
                    make_float2(acc[mt][nt][0], acc[mt][nt][1]);
            if (r0 + 8 < n)
                *(float2*)(g_A + (size_t)(r0 + 8) * D + col) =
                    make_float2(acc[mt][nt][2], acc[mt][nt][3]);
        }
    }
}

// ---------------------------------------------------------------------------
// fused aggregate: warp per node.
// ---------------------------------------------------------------------------
__global__ void k_agg(const float* __restrict__ bias,
                      const int* __restrict__ batch, int doPool) {
    int gt = blockIdx.x * blockDim.x + threadIdx.x;
    int w = gt >> 5;
    if (w >= N_NODES) return;
    int lane = gt & 31;

    float dv = g_dis[w];
    float sn = dv * dv;
    float4 h = ((const float4*)(g_A + (size_t)w * D))[lane];
    float4 acc = make_float4(sn * h.x, sn * h.y, sn * h.z, sn * h.w);

    int beg = g_rowptr[w];
    int end = beg + g_cnt[w];
    for (int k = beg; k < end; k++) {
        int s = g_csrc[k];
        float nr = g_cnrm[k];
        float4 v = ((const float4*)(g_A + (size_t)s * D))[lane];
        acc.x += nr * v.x; acc.y += nr * v.y;
        acc.z += nr * v.z; acc.w += nr * v.w;
    }

    float4 bb = ((const float4*)bias)[lane];
    acc.x = fmaxf(acc.x + bb.x, 0.f);
    acc.y = fmaxf(acc.y + bb.y, 0.f);
    acc.z = fmaxf(acc.z + bb.z, 0.f);
    acc.w = fmaxf(acc.w + bb.w, 0.f);
    ((float4*)(g_B + (size_t)w * D))[lane] = acc;

    if (doPool) {
        float* pp = g_pool + (size_t)batch[w] * D + lane * 4;
        asm volatile("red.global.add.v4.f32 [%0], {%1,%2,%3,%4};"
                     :: "l"(pp), "f"(acc.x), "f"(acc.y), "f"(acc.z), "f"(acc.w)
                     : "memory");
    }
}

// ---------------------------------------------------------------------------
// head: pooled mean -> linear(128->10) -> log_softmax. One warp per graph.
// ---------------------------------------------------------------------------
__global__ void k_head(const float* __restrict__ Wf, const float* __restrict__ bf,
                       float* __restrict__ out) {
    int g = blockIdx.x;
    int lane = threadIdx.x;
    float inv = 1.0f / fmaxf(g_pcnt[g], 1.0f);
    float logit = -INFINITY;
    if (lane < O) {
        float s = bf[lane];
        const float* pr = g_pool + (size_t)g * D;
#pragma unroll 8
        for (int k = 0; k < D; k++)
            s += pr[k] * inv * Wf[k * O + lane];
        logit = s;
    }
    float m = logit;
#pragma unroll
    for (int o = 16; o; o >>= 1) m = fmaxf(m, __shfl_xor_sync(0xffffffffu, m, o));
    float e = (lane < O) ? expf(logit - m) : 0.0f;
    float se = e;
#pragma unroll
    for (int o = 16; o; o >>= 1) se += __shfl_xor_sync(0xffffffffu, se, o);
    if (lane < O) out[g * O + lane] = logit - m - logf(se);
}

// ---------------------------------------------------------------------------
extern "C" void kernel_launch(void* const* d_in, const int* in_sizes, int n_in,
                              void* d_out, int out_size) {
    const float* x     = (const float*)d_in[0];
    const int*   ei    = (const int*)d_in[1];
    const int*   batch = (const int*)d_in[2];
    const float* W0 = (const float*)d_in[3];
    const float* b0 = (const float*)d_in[4];
    const float* W1 = (const float*)d_in[5];
    const float* b1 = (const float*)d_in[6];
    const float* W2 = (const float*)d_in[7];
    const float* b2 = (const float*)d_in[8];
    const float* Wf = (const float*)d_in[9];
    const float* bf = (const float*)d_in[10];
    float* out = (float*)d_out;

    cudaFuncSetAttribute(k_gemm_tc, cudaFuncAttributeMaxDynamicSharedMemorySize,
                         SMEM_GEMM_BYTES);

    // build degree / dis / CSR / pool counts
    k_prep<<<(G * D + 255) / 256, 256>>>();
    k_count<<<(N_EDGES + 255) / 256, 256>>>(ei);
    k_scan1<<<NBLK, 256>>>();
    k_scan2<<<1, 256>>>();
    k_scan3<<<NBLK, 256>>>();
    k_fill<<<(N_EDGES + 255) / 256, 256>>>(ei);
    k_pcnt<<<(G + 255) / 256, 256>>>(batch);

    const float* Ws[3] = {W0, W1, W2};
    const float* bs[3] = {b0, b1, b2};
    int agg_blocks = (N_NODES * 32 + 255) / 256;

    for (int l = 0; l < 3; l++) {
        k_gemm_tc<<<GEMM_TILES, 256, SMEM_GEMM_BYTES>>>(x, Ws[l], l == 0 ? 1 : 0, N_NODES);
        k_agg<<<agg_blocks, 256>>>(bs[l], batch, l == 2 ? 1 : 0);
    }

    k_head<<<G, 32>>>(Wf, bf, out);
}